// round 5
// baseline (speedup 1.0000x reference)
#include <cuda_runtime.h>
#include <cuda_fp16.h>
#include <cstdint>

// Problem constants
#define NA   2048           // atoms
#define ND   64             // depth
#define NF   12             // filters
#define KTOT (NA * NF)      // 24576, GEMM K
#define DP2  (ND + 2)       // 66
#define FSTR (NF * DP2)     // 792, filters stride per o

// GEMM tiling
#define MTILE   128
#define SPLITS  8
#define KCHUNK  (KTOT / SPLITS)   // 3072
#define KB      32                // k per smem stage
#define NSTAGES (KCHUNK / KB)     // 96
#define SPAD    40                // row stride in halves (80B, 16B-aligned)

// ---------------- device scratch (static module allocations, no runtime alloc) ---------
__device__ __align__(16) __half g_connH[(size_t)NA * KTOT];     // ~100.7 MB fp16 conn
__device__ __align__(16) float  g_Wf[(size_t)ND * KTOT];        // W fp32 [o][k], 6.3 MB
__device__ __align__(16) __half g_WT[(size_t)ND * KTOT];        // W fp16 scaled [o][k], 3.1 MB
__device__ __align__(16) float  g_Ft[2 * NF * ND * ND];         // filters transposed [L][f][d][o]
__device__ __align__(16) float  g_bias[2][NA * ND];             // per-filter-pair bias
__device__ __align__(16) float  g_act[NA * ND];                 // activation between convs
__device__ __align__(16) float  g_part[(NA / MTILE) * SPLITS * MTILE * ND]; // split-K partials
__device__ unsigned int g_wmax_bits;                            // max|W| as float bits
__device__ float g_scale, g_invscale;                           // W scaling (power of 2)

// ---------------- helpers ----------------
__device__ __forceinline__ uint32_t smem_u32(const void* p) {
    return (uint32_t)__cvta_generic_to_shared(p);
}

__device__ __forceinline__ void ldmx4(uint32_t* r, uint32_t addr) {
    asm volatile("ldmatrix.sync.aligned.m8n8.x4.shared.b16 {%0,%1,%2,%3}, [%4];"
                 : "=r"(r[0]), "=r"(r[1]), "=r"(r[2]), "=r"(r[3]) : "r"(addr));
}

__device__ __forceinline__ void mma16816(float* c, const uint32_t* a, uint32_t b0, uint32_t b1) {
    asm volatile(
        "mma.sync.aligned.m16n8k16.row.col.f32.f16.f16.f32 "
        "{%0,%1,%2,%3}, {%4,%5,%6,%7}, {%8,%9}, {%0,%1,%2,%3};"
        : "+f"(c[0]), "+f"(c[1]), "+f"(c[2]), "+f"(c[3])
        : "r"(a[0]), "r"(a[1]), "r"(a[2]), "r"(a[3]), "r"(b0), "r"(b1));
}

// ---------------- kernel 1: fp32 conn -> fp16 ----------------
__global__ void k_conv_half(const float4* __restrict__ src, int n4) {
    int i = blockIdx.x * blockDim.x + threadIdx.x;
    int stride = gridDim.x * blockDim.x;
    uint2* dst = reinterpret_cast<uint2*>(g_connH);
    for (; i < n4; i += stride) {
        float4 v = src[i];
        __half2 h0 = __floats2half2_rn(v.x, v.y);
        __half2 h1 = __floats2half2_rn(v.z, v.w);
        uint2 u;
        u.x = *reinterpret_cast<uint32_t*>(&h0);
        u.y = *reinterpret_cast<uint32_t*>(&h1);
        dst[i] = u;
    }
}

// ---------------- kernel 2: transpose filters -> Ft[L][f][d][o] ----------------
__global__ void k_prep_filters(const float* __restrict__ f0, const float* __restrict__ f1) {
    int idx = blockIdx.x * blockDim.x + threadIdx.x;
    int total = 2 * NF * ND * ND;
    if (idx >= total) return;
    int o = idx & 63;
    int d = (idx >> 6) & 63;
    int f = (idx >> 12) % NF;
    int L = idx / (NF * ND * ND);
    const float* src = L ? f1 : f0;
    g_Ft[idx] = src[o * FSTR + f * DP2 + d];
}

// ---------------- kernel 3: bias[L][a][o] = sum_{f,j} bond[a,f,j] * filt_L[o,f,D+j] ----
__global__ void k_bias(const float* __restrict__ bond,
                       const float* __restrict__ f0, const float* __restrict__ f1) {
    __shared__ float sb[NF * 2];
    int a = blockIdx.x;
    int o = threadIdx.x;
    if (o < NF * 2) sb[o] = bond[a * NF * 2 + o];
    __syncthreads();
    for (int L = 0; L < 2; L++) {
        const float* flt = L ? f1 : f0;
        float s = 0.f;
#pragma unroll
        for (int f = 0; f < NF; f++) {
            s += sb[f * 2 + 0] * flt[o * FSTR + f * DP2 + ND + 0];
            s += sb[f * 2 + 1] * flt[o * FSTR + f * DP2 + ND + 1];
        }
        g_bias[L][a * ND + o] = s;
    }
}

// ---------------- reset max tracker ----------------
__global__ void k_reset() { g_wmax_bits = 0u; }

// ---------------- kernel 4: Wf[o][k] = sum_d act[n,d] * Ft[L][f][d][o], k = n*F+f -----
// grid (64 o-blocks, 24 k-chunks), 256 threads, 4 k per thread; block-max -> atomicMax
__global__ void k_W(const float* __restrict__ xin, int useX, int L) {
    __shared__ float sF[NF * ND];   // Ft column for this o
    __shared__ float smax[8];
    int o = blockIdx.x;
    int t = threadIdx.x;
    const float* act = useX ? xin : g_act;
    for (int i = t; i < NF * ND; i += 256)
        sF[i] = g_Ft[(L * NF * ND + i) * ND + o];
    __syncthreads();
    int kbase = blockIdx.y * 1024;
    float mx = 0.f;
#pragma unroll
    for (int j = 0; j < 4; j++) {
        int k = kbase + j * 256 + t;
        int n = k / NF;
        int f = k - n * NF;
        const float4* ar = reinterpret_cast<const float4*>(act + n * ND);
        const float* fr = &sF[f * ND];
        float s = 0.f;
#pragma unroll
        for (int d4 = 0; d4 < 16; d4++) {
            float4 v = ar[d4];
            s += v.x * fr[d4 * 4 + 0] + v.y * fr[d4 * 4 + 1]
               + v.z * fr[d4 * 4 + 2] + v.w * fr[d4 * 4 + 3];
        }
        g_Wf[(size_t)o * KTOT + k] = s;
        mx = fmaxf(mx, fabsf(s));
    }
    // warp + block max reduction, then one atomic per block
#pragma unroll
    for (int off = 16; off; off >>= 1)
        mx = fmaxf(mx, __shfl_xor_sync(0xffffffffu, mx, off));
    if ((t & 31) == 0) smax[t >> 5] = mx;
    __syncthreads();
    if (t == 0) {
#pragma unroll
        for (int w = 1; w < 8; w++) mx = fmaxf(mx, smax[w]);
        atomicMax(&g_wmax_bits, __float_as_uint(mx));
    }
}

// ---------------- kernel 4b: compute power-of-2 scale so max|W|*scale <= 16384 --------
__global__ void k_scale() {
    float wmax = __uint_as_float(g_wmax_bits);
    float sc = 1.f;
    // only downscale; powers of two are exact
    while (wmax * sc > 16384.f) sc *= 0.5f;
    g_scale = sc;
    g_invscale = 1.f / sc;
}

// ---------------- kernel 4c: convert W fp32 -> fp16 with scale ----------------
__global__ void k_Wh(int n4) {
    int i = blockIdx.x * blockDim.x + threadIdx.x;
    if (i >= n4) return;
    float sc = g_scale;
    float4 v = reinterpret_cast<const float4*>(g_Wf)[i];
    __half2 h0 = __floats2half2_rn(v.x * sc, v.y * sc);
    __half2 h1 = __floats2half2_rn(v.z * sc, v.w * sc);
    uint2 u;
    u.x = *reinterpret_cast<uint32_t*>(&h0);
    u.y = *reinterpret_cast<uint32_t*>(&h1);
    reinterpret_cast<uint2*>(g_WT)[i] = u;
}

// ---------------- kernel 5: split-K GEMM  part[mt,sp] = connH_tile @ WT^T ----------------
// grid (16 m-tiles, 8 splits), 256 threads = 8 warps in 4x2 layout, warp tile 32x32
__global__ __launch_bounds__(256, 1) void k_gemm() {
    __shared__ __align__(16) __half sA[2][MTILE][SPAD];
    __shared__ __align__(16) __half sB[2][ND][SPAD];

    int t = threadIdx.x;
    int mt = blockIdx.x, sp = blockIdx.y;
    int K0 = sp * KCHUNK;
    int lane = t & 31, w = t >> 5;
    int wm = w & 3, wn = w >> 2;

    float acc[2][4][4];
#pragma unroll
    for (int i = 0; i < 2; i++)
#pragma unroll
        for (int j = 0; j < 4; j++)
#pragma unroll
            for (int q = 0; q < 4; q++) acc[i][j][q] = 0.f;

    auto LOAD = [&](int buf, int kb) {
#pragma unroll
        for (int j = 0; j < 2; j++) {
            int idx = t + j * 256;
            int row = idx >> 2, cc = idx & 3;
            const __half* src = g_connH + (size_t)(mt * MTILE + row) * KTOT + K0 + kb + cc * 8;
            uint32_t dst = smem_u32(&sA[buf][row][cc * 8]);
            asm volatile("cp.async.cg.shared.global [%0], [%1], 16;" :: "r"(dst), "l"(src));
        }
        {
            int row = t >> 2, cc = t & 3;
            const __half* src = g_WT + (size_t)row * KTOT + K0 + kb + cc * 8;
            uint32_t dst = smem_u32(&sB[buf][row][cc * 8]);
            asm volatile("cp.async.cg.shared.global [%0], [%1], 16;" :: "r"(dst), "l"(src));
        }
        asm volatile("cp.async.commit_group;");
    };

    int ar = (lane & 7) + ((lane >> 3) & 1) * 8;   // A-fragment row within m16
    int asel = (lane >> 4) * 8;                    // A-fragment k-half
    int br = (lane & 7) + (lane >> 4) * 8;         // B n-row select
    int bsel = ((lane >> 3) & 1) * 8;              // B k-half

    auto COMPUTE = [&](int buf) {
#pragma unroll
        for (int kk = 0; kk < KB; kk += 16) {
            uint32_t a[2][4], b[2][4];
#pragma unroll
            for (int mi = 0; mi < 2; mi++) {
                uint32_t ad = smem_u32(&sA[buf][wm * 32 + mi * 16 + ar][kk + asel]);
                ldmx4(a[mi], ad);
            }
#pragma unroll
            for (int p = 0; p < 2; p++) {
                uint32_t bd = smem_u32(&sB[buf][wn * 32 + p * 16 + br][kk + bsel]);
                ldmx4(b[p], bd);
            }
#pragma unroll
            for (int mi = 0; mi < 2; mi++)
#pragma unroll
                for (int nt = 0; nt < 4; nt++)
                    mma16816(acc[mi][nt], a[mi], b[nt >> 1][(nt & 1) * 2], b[nt >> 1][(nt & 1) * 2 + 1]);
        }
    };

    LOAD(0, 0);
    for (int s = 0; s < NSTAGES; s++) {
        if (s + 1 < NSTAGES) {
            LOAD((s + 1) & 1, (s + 1) * KB);
            asm volatile("cp.async.wait_group 1;");
        } else {
            asm volatile("cp.async.wait_group 0;");
        }
        __syncthreads();
        COMPUTE(s & 1);
        __syncthreads();
    }

    int g = lane >> 2, q = lane & 3;
    size_t pbase = (size_t)(mt * SPLITS + sp) * MTILE * ND;
#pragma unroll
    for (int mi = 0; mi < 2; mi++)
#pragma unroll
        for (int nt = 0; nt < 4; nt++) {
            int lrow = wm * 32 + mi * 16 + g;
            int col = wn * 32 + nt * 8 + q * 2;
            float2* p0 = reinterpret_cast<float2*>(&g_part[pbase + (size_t)lrow * ND + col]);
            *p0 = make_float2(acc[mi][nt][0], acc[mi][nt][1]);
            float2* p1 = reinterpret_cast<float2*>(&g_part[pbase + (size_t)(lrow + 8) * ND + col]);
            *p1 = make_float2(acc[mi][nt][2], acc[mi][nt][3]);
        }
}

// ---------------- kernel 6: split-K reduce * invscale + bias (+x) + ReLU ----------------
__global__ void k_reduce(int L, int addX, int writeOut,
                         const float* __restrict__ x, float* __restrict__ dout) {
    int idx = blockIdx.x * blockDim.x + threadIdx.x;   // a*64 + o
    int a = idx >> 6;
    int o = idx & 63;
    int mtl = a >> 7;            // m-tile
    int lr = a & 127;            // row within tile
    float s = 0.f;
#pragma unroll
    for (int sp = 0; sp < SPLITS; sp++)
        s += g_part[(size_t)(mtl * SPLITS + sp) * MTILE * ND + (size_t)lr * ND + o];
    float v = s * g_invscale + g_bias[L][idx];
    if (addX) v += x[idx];
    v = fmaxf(v, 0.f);
    g_act[idx] = v;
    if (writeOut) dout[idx] = v;
}

// ---------------- launcher ----------------
extern "C" void kernel_launch(void* const* d_in, const int* in_sizes, int n_in,
                              void* d_out, int out_size) {
    const float* x    = (const float*)d_in[0];   // (2048, 64)
    const float* conn = (const float*)d_in[1];   // (2048, 2048, 12)
    const float* bond = (const float*)d_in[2];   // (2048, 12, 2)
    const float* f0   = (const float*)d_in[3];   // (64, 12, 66)
    const float* f1   = (const float*)d_in[4];   // (64, 12, 66)
    float* out = (float*)d_out;                  // (2048, 64)

    // prep
    int n4 = (NA * NA * NF) / 4;
    k_conv_half<<<6144, 256>>>((const float4*)conn, n4);
    k_prep_filters<<<(2 * NF * ND * ND + 255) / 256, 256>>>(f0, f1);
    k_bias<<<NA, ND>>>(bond, f0, f1);

    // 4 chemconvs: c0: relu(P); c1: relu(P+x); c2: relu(P); c3: relu(P+x) -> out
    int wn4 = (ND * KTOT) / 4;
    for (int c = 0; c < 4; c++) {
        int L = c >> 1;
        k_reset<<<1, 1>>>();
        k_W<<<dim3(64, 24), 256>>>(x, (c == 0) ? 1 : 0, L);
        k_scale<<<1, 1>>>();
        k_Wh<<<(wn4 + 255) / 256, 256>>>(wn4);
        k_gemm<<<dim3(NA / MTILE, SPLITS), 256>>>();
        k_reduce<<<(NA * ND) / 256, 256>>>(L, c & 1, (c == 3) ? 1 : 0, x, out);
    }
}

// round 8
// speedup vs baseline: 1.0337x; 1.0337x over previous
#include <cuda_runtime.h>
#include <cuda_fp16.h>
#include <cstdint>

// Problem constants
#define NA   2048           // atoms
#define ND   64             // depth
#define NF   12             // filters
#define KTOT (NA * NF)      // 24576, GEMM K
#define DP2  (ND + 2)       // 66
#define FSTR (NF * DP2)     // 792, filters stride per o

// GEMM tiling
#define MTILE   128
#define SPLITS  8
#define KCHUNK  (KTOT / SPLITS)   // 3072
#define KB      32                // k per smem stage
#define NSTAGES (KCHUNK / KB)     // 96
#define SPAD    40                // row stride in halves (80B -> conflict-free ldmatrix)
#define PIPE    5                 // cp.async pipeline depth
#define GEMM_SMEM (PIPE * (MTILE + ND) * SPAD * 2)   // 76800 B dynamic smem

// ---------------- device scratch (static module allocations, no runtime alloc) ---------
__device__ __align__(16) __half g_connH[(size_t)NA * KTOT];     // ~100.7 MB fp16 conn
__device__ __align__(16) __half g_WT[(size_t)ND * KTOT];        // W fp16 scaled [o][k]
__device__ __align__(16) float  g_Ft[2 * NF * ND * ND];         // filters transposed [L][f][d][o]
__device__ __align__(16) float  g_bias[2][NA * ND];             // per-filter-pair bias
__device__ __align__(16) float  g_act[NA * ND];                 // activation between convs
__device__ __align__(16) float  g_part[(NA / MTILE) * SPLITS * MTILE * ND]; // split-K partials
__device__ unsigned int g_amax_bits[5];                         // max|act| per conv stage (bits)
__device__ float g_B[2];                                        // max_{o,f} sum_d |filt|

// ---------------- helpers ----------------
__device__ __forceinline__ uint32_t smem_u32(const void* p) {
    return (uint32_t)__cvta_generic_to_shared(p);
}

__device__ __forceinline__ void ldmx4(uint32_t* r, uint32_t addr) {
    asm volatile("ldmatrix.sync.aligned.m8n8.x4.shared.b16 {%0,%1,%2,%3}, [%4];"
                 : "=r"(r[0]), "=r"(r[1]), "=r"(r[2]), "=r"(r[3]) : "r"(addr));
}

__device__ __forceinline__ void mma16816(float* c, const uint32_t* a, uint32_t b0, uint32_t b1) {
    asm volatile(
        "mma.sync.aligned.m16n8k16.row.col.f32.f16.f16.f32 "
        "{%0,%1,%2,%3}, {%4,%5,%6,%7}, {%8,%9}, {%0,%1,%2,%3};"
        : "+f"(c[0]), "+f"(c[1]), "+f"(c[2]), "+f"(c[3])
        : "r"(a[0]), "r"(a[1]), "r"(a[2]), "r"(a[3]), "r"(b0), "r"(b1));
}

// scale = 2^(14-e) if bound >= 2^14 else 1  (power of 2, exact)
__device__ __forceinline__ float w_scale(int c, int L) {
    float bound = __uint_as_float(g_amax_bits[c]) * g_B[L];
    int e; frexpf(bound, &e);
    return (e > 14) ? ldexpf(1.f, 14 - e) : 1.f;
}
__device__ __forceinline__ float w_invscale(int c, int L) {
    float bound = __uint_as_float(g_amax_bits[c]) * g_B[L];
    int e; frexpf(bound, &e);
    return (e > 14) ? ldexpf(1.f, e - 14) : 1.f;
}

// ---------------- kernel 1: fp32 conn -> fp16 ----------------
__global__ void k_conv_half(const float4* __restrict__ src, int n4) {
    int i = blockIdx.x * blockDim.x + threadIdx.x;
    int stride = gridDim.x * blockDim.x;
    uint2* dst = reinterpret_cast<uint2*>(g_connH);
    for (; i < n4; i += stride) {
        float4 v = src[i];
        __half2 h0 = __floats2half2_rn(v.x, v.y);
        __half2 h1 = __floats2half2_rn(v.z, v.w);
        uint2 u;
        u.x = *reinterpret_cast<uint32_t*>(&h0);
        u.y = *reinterpret_cast<uint32_t*>(&h1);
        dst[i] = u;
    }
}

// ---------------- kernel 2: transpose filters -> Ft[L][f][d][o] ----------------
__global__ void k_prep_filters(const float* __restrict__ f0, const float* __restrict__ f1) {
    int idx = blockIdx.x * blockDim.x + threadIdx.x;
    int total = 2 * NF * ND * ND;
    if (idx >= total) return;
    int o = idx & 63;
    int d = (idx >> 6) & 63;
    int f = (idx >> 12) % NF;
    int L = idx / (NF * ND * ND);
    const float* src = L ? f1 : f0;
    g_Ft[idx] = src[o * FSTR + f * DP2 + d];
}

// ---------------- kernel 2b: init — filter colsum bounds + max|x| + zero amax slots ----
// grid = 3 blocks x 256: blocks 0,1 -> g_B[L]; block 2 -> amax(x) into slot 0, zero 1..4
__global__ void k_init(const float* __restrict__ x,
                       const float* __restrict__ f0, const float* __restrict__ f1) {
    __shared__ float sred[256];
    int t = threadIdx.x;
    int b = blockIdx.x;
    if (b < 2) {
        const float* flt = b ? f1 : f0;
        float mx = 0.f;
        // 64*12 = 768 (o,f) colsums over d; 3 per thread
        for (int i = t; i < ND * NF; i += 256) {
            int o = i / NF, f = i - o * NF;
            const float* p = flt + o * FSTR + f * DP2;
            float s = 0.f;
#pragma unroll
            for (int d = 0; d < ND; d++) s += fabsf(p[d]);
            mx = fmaxf(mx, s);
        }
        sred[t] = mx;
        __syncthreads();
        for (int off = 128; off; off >>= 1) {
            if (t < off) sred[t] = fmaxf(sred[t], sred[t + off]);
            __syncthreads();
        }
        if (t == 0) g_B[b] = sred[0];
    } else {
        float mx = 0.f;
        for (int i = t; i < NA * ND; i += 256) mx = fmaxf(mx, fabsf(x[i]));
        sred[t] = mx;
        __syncthreads();
        for (int off = 128; off; off >>= 1) {
            if (t < off) sred[t] = fmaxf(sred[t], sred[t + off]);
            __syncthreads();
        }
        if (t == 0) {
            g_amax_bits[0] = __float_as_uint(sred[0]);
            g_amax_bits[1] = 0u; g_amax_bits[2] = 0u;
            g_amax_bits[3] = 0u; g_amax_bits[4] = 0u;
        }
    }
}

// ---------------- kernel 3: bias[L][a][o] = sum_{f,j} bond[a,f,j] * filt_L[o,f,D+j] ----
__global__ void k_bias(const float* __restrict__ bond,
                       const float* __restrict__ f0, const float* __restrict__ f1) {
    __shared__ float sb[NF * 2];
    int a = blockIdx.x;
    int o = threadIdx.x;
    if (o < NF * 2) sb[o] = bond[a * NF * 2 + o];
    __syncthreads();
    for (int L = 0; L < 2; L++) {
        const float* flt = L ? f1 : f0;
        float s = 0.f;
#pragma unroll
        for (int f = 0; f < NF; f++) {
            s += sb[f * 2 + 0] * flt[o * FSTR + f * DP2 + ND + 0];
            s += sb[f * 2 + 1] * flt[o * FSTR + f * DP2 + ND + 1];
        }
        g_bias[L][a * ND + o] = s;
    }
}

// ---------------- kernel 4: WT[o][k] = scale * sum_d act[n,d] * Ft[L][f][d][o] ---------
// grid (64 o-blocks, 24 k-chunks), 256 threads, 4 k/thread -> coalesced fp16 writes
__global__ void k_W(const float* __restrict__ xin, int c, int L) {
    __shared__ float sF[NF * ND];   // Ft column for this o
    int o = blockIdx.x;
    int t = threadIdx.x;
    const float* act = (c == 0) ? xin : g_act;
    float sc = w_scale(c, L);
    for (int i = t; i < NF * ND; i += 256)
        sF[i] = g_Ft[(L * NF * ND + i) * ND + o];
    __syncthreads();
    int kbase = blockIdx.y * 1024;
#pragma unroll
    for (int j = 0; j < 4; j++) {
        int k = kbase + j * 256 + t;
        int n = k / NF;
        int f = k - n * NF;
        const float4* ar = reinterpret_cast<const float4*>(act + n * ND);
        const float* fr = &sF[f * ND];
        float s = 0.f;
#pragma unroll
        for (int d4 = 0; d4 < 16; d4++) {
            float4 v = ar[d4];
            s += v.x * fr[d4 * 4 + 0] + v.y * fr[d4 * 4 + 1]
               + v.z * fr[d4 * 4 + 2] + v.w * fr[d4 * 4 + 3];
        }
        g_WT[(size_t)o * KTOT + k] = __float2half_rn(s * sc);
    }
}

// ---------------- kernel 5: split-K GEMM, 5-stage cp.async pipeline ----------------
// grid (16 m-tiles, 8 splits), 256 threads = 8 warps (4x2), warp tile 32x32
__global__ __launch_bounds__(256, 1) void k_gemm() {
    extern __shared__ __align__(16) __half dyn[];
    __half* sAb = dyn;                          // [PIPE][MTILE][SPAD]
    __half* sBb = dyn + PIPE * MTILE * SPAD;    // [PIPE][ND][SPAD]

    int t = threadIdx.x;
    int mt = blockIdx.x, sp = blockIdx.y;
    int K0 = sp * KCHUNK;
    int lane = t & 31, w = t >> 5;
    int wm = w & 3, wn = w >> 2;

    float acc[2][4][4];
#pragma unroll
    for (int i = 0; i < 2; i++)
#pragma unroll
        for (int j = 0; j < 4; j++)
#pragma unroll
            for (int q = 0; q < 4; q++) acc[i][j][q] = 0.f;

    auto LOAD = [&](int buf, int kb) {
        __half* A = sAb + buf * MTILE * SPAD;
        __half* B = sBb + buf * ND * SPAD;
#pragma unroll
        for (int j = 0; j < 2; j++) {
            int idx = t + j * 256;
            int row = idx >> 2, cc = idx & 3;
            const __half* src = g_connH + (size_t)(mt * MTILE + row) * KTOT + K0 + kb + cc * 8;
            uint32_t dst = smem_u32(A + row * SPAD + cc * 8);
            asm volatile("cp.async.cg.shared.global [%0], [%1], 16;" :: "r"(dst), "l"(src));
        }
        {
            int row = t >> 2, cc = t & 3;
            const __half* src = g_WT + (size_t)row * KTOT + K0 + kb + cc * 8;
            uint32_t dst = smem_u32(B + row * SPAD + cc * 8);
            asm volatile("cp.async.cg.shared.global [%0], [%1], 16;" :: "r"(dst), "l"(src));
        }
        asm volatile("cp.async.commit_group;");
    };

    int ar = (lane & 7) + ((lane >> 3) & 1) * 8;   // A-fragment row within m16
    int asel = (lane >> 4) * 8;                    // A-fragment k-half
    int br = (lane & 7) + (lane >> 4) * 8;         // B n-row select
    int bsel = ((lane >> 3) & 1) * 8;              // B k-half

    auto COMPUTE = [&](int buf) {
        __half* A = sAb + buf * MTILE * SPAD;
        __half* B = sBb + buf * ND * SPAD;
#pragma unroll
        for (int kk = 0; kk < KB; kk += 16) {
            uint32_t a[2][4], b[2][4];
#pragma unroll
            for (int mi = 0; mi < 2; mi++) {
                uint32_t ad = smem_u32(A + (wm * 32 + mi * 16 + ar) * SPAD + kk + asel);
                ldmx4(a[mi], ad);
            }
#pragma unroll
            for (int p = 0; p < 2; p++) {
                uint32_t bd = smem_u32(B + (wn * 32 + p * 16 + br) * SPAD + kk + bsel);
                ldmx4(b[p], bd);
            }
#pragma unroll
            for (int mi = 0; mi < 2; mi++)
#pragma unroll
                for (int nt = 0; nt < 4; nt++)
                    mma16816(acc[mi][nt], a[mi], b[nt >> 1][(nt & 1) * 2], b[nt >> 1][(nt & 1) * 2 + 1]);
        }
    };

    // prologue: PIPE-1 stages in flight
#pragma unroll
    for (int s = 0; s < PIPE - 1; s++) LOAD(s, s * KB);

    int buf = 0;
    for (int s = 0; s < NSTAGES; s++) {
        asm volatile("cp.async.wait_group %0;" :: "n"(PIPE - 2));
        __syncthreads();
        int nxt = s + PIPE - 1;
        if (nxt < NSTAGES) {
            int wb = buf + (PIPE - 1); if (wb >= PIPE) wb -= PIPE;
            LOAD(wb, nxt * KB);
        }
        COMPUTE(buf);
        if (++buf == PIPE) buf = 0;
    }

    // epilogue: write partials (unique writer per element -> deterministic)
    int g = lane >> 2, q = lane & 3;
    size_t pbase = (size_t)(mt * SPLITS + sp) * MTILE * ND;
#pragma unroll
    for (int mi = 0; mi < 2; mi++)
#pragma unroll
        for (int nt = 0; nt < 4; nt++) {
            int lrow = wm * 32 + mi * 16 + g;
            int col = wn * 32 + nt * 8 + q * 2;
            float2* p0 = reinterpret_cast<float2*>(&g_part[pbase + (size_t)lrow * ND + col]);
            *p0 = make_float2(acc[mi][nt][0], acc[mi][nt][1]);
            float2* p1 = reinterpret_cast<float2*>(&g_part[pbase + (size_t)(lrow + 8) * ND + col]);
            *p1 = make_float2(acc[mi][nt][2], acc[mi][nt][3]);
        }
}

// ---------------- kernel 6: split-K reduce * invscale + bias (+x) + ReLU + amax --------
__global__ void k_reduce(int c, int L, int addX, int writeOut,
                         const float* __restrict__ x, float* __restrict__ dout) {
    __shared__ float smax[8];
    int t = threadIdx.x;
    int idx = blockIdx.x * 256 + t;   // a*64 + o
    int a = idx >> 6;
    int o = idx & 63;
    int mtl = a >> 7;            // m-tile
    int lr = a & 127;            // row within tile
    float inv = w_invscale(c, L);
    float s = 0.f;
#pragma unroll
    for (int sp = 0; sp < SPLITS; sp++)
        s += g_part[(size_t)(mtl * SPLITS + sp) * MTILE * ND + (size_t)lr * ND + o];
    float v = s * inv + g_bias[L][idx];
    if (addX) v += x[idx];
    v = fmaxf(v, 0.f);
    g_act[idx] = v;
    if (writeOut) dout[idx] = v;
    // track max|act| for next conv's W scaling (deterministic: uint atomicMax)
    float mx = v;
#pragma unroll
    for (int off = 16; off; off >>= 1)
        mx = fmaxf(mx, __shfl_xor_sync(0xffffffffu, mx, off));
    if ((t & 31) == 0) smax[t >> 5] = mx;
    __syncthreads();
    if (t == 0) {
#pragma unroll
        for (int ww = 1; ww < 8; ww++) mx = fmaxf(mx, smax[ww]);
        atomicMax(&g_amax_bits[c + 1], __float_as_uint(mx));
    }
}

// ---------------- launcher ----------------
extern "C" void kernel_launch(void* const* d_in, const int* in_sizes, int n_in,
                              void* d_out, int out_size) {
    const float* x    = (const float*)d_in[0];   // (2048, 64)
    const float* conn = (const float*)d_in[1];   // (2048, 2048, 12)
    const float* bond = (const float*)d_in[2];   // (2048, 12, 2)
    const float* f0   = (const float*)d_in[3];   // (64, 12, 66)
    const float* f1   = (const float*)d_in[4];   // (64, 12, 66)
    float* out = (float*)d_out;                  // (2048, 64)

    cudaFuncSetAttribute(k_gemm, cudaFuncAttributeMaxDynamicSharedMemorySize, GEMM_SMEM);

    // prep
    int n4 = (NA * NA * NF) / 4;
    k_conv_half<<<6144, 256>>>((const float4*)conn, n4);
    k_prep_filters<<<(2 * NF * ND * ND + 255) / 256, 256>>>(f0, f1);
    k_init<<<3, 256>>>(x, f0, f1);
    k_bias<<<NA, ND>>>(bond, f0, f1);

    // 4 chemconvs: c0: relu(P); c1: relu(P+x); c2: relu(P); c3: relu(P+x) -> out
    for (int c = 0; c < 4; c++) {
        int L = c >> 1;
        k_W<<<dim3(64, 24), 256>>>(x, c, L);
        k_gemm<<<dim3(NA / MTILE, SPLITS), 256, GEMM_SMEM>>>();
        k_reduce<<<(NA * ND) / 256, 256>>>(c, L, c & 1, (c == 3) ? 1 : 0, x, out);
    }
}

// round 10
// speedup vs baseline: 1.1230x; 1.0864x over previous
#include <cuda_runtime.h>
#include <cuda_fp16.h>
#include <cstdint>

// Problem constants
#define NA   2048           // atoms
#define ND   64             // depth
#define NF   12             // filters
#define KTOT (NA * NF)      // 24576, GEMM K
#define DP2  (ND + 2)       // 66
#define FSTR (NF * DP2)     // 792

// GEMM tiling
#define MTILE   128
#define SPLITS  8
#define KCHUNK  (KTOT / SPLITS)   // 3072
#define KB      64                // k per smem stage (doubled vs R8 -> half the barriers)
#define NSTAGES (KCHUNK / KB)     // 48
#define SPAD    72                // row stride in halves (144B; 8-row ldmatrix conflict-free)
#define PIPE    4                 // cp.async pipeline depth
#define GEMM_SMEM (PIPE * (MTILE + ND) * SPAD * 2)   // 110592 B dynamic smem

// ---------------- device scratch (static module allocations, no runtime alloc) ---------
__device__ __align__(16) __half g_connH[(size_t)NA * KTOT];     // ~100.7 MB fp16 conn
__device__ __align__(16) __half g_WT[(size_t)ND * KTOT];        // W fp16 scaled [o][k]
__device__ __align__(16) float  g_Ft[2 * NF * ND * ND];         // filters transposed [L][f][d][o]
__device__ __align__(16) float  g_bias[2][NA * ND];
__device__ __align__(16) float  g_act[NA * ND];
__device__ __align__(16) float  g_part[(NA / MTILE) * SPLITS * MTILE * ND];
__device__ unsigned int g_amax_bits[5];
__device__ float g_B[2];

// ---------------- helpers ----------------
__device__ __forceinline__ uint32_t smem_u32(const void* p) {
    return (uint32_t)__cvta_generic_to_shared(p);
}

__device__ __forceinline__ void ldmx4(uint32_t* r, uint32_t addr) {
    asm volatile("ldmatrix.sync.aligned.m8n8.x4.shared.b16 {%0,%1,%2,%3}, [%4];"
                 : "=r"(r[0]), "=r"(r[1]), "=r"(r[2]), "=r"(r[3]) : "r"(addr));
}

__device__ __forceinline__ void mma16816(float* c, const uint32_t* a, uint32_t b0, uint32_t b1) {
    asm volatile(
        "mma.sync.aligned.m16n8k16.row.col.f32.f16.f16.f32 "
        "{%0,%1,%2,%3}, {%4,%5,%6,%7}, {%8,%9}, {%0,%1,%2,%3};"
        : "+f"(c[0]), "+f"(c[1]), "+f"(c[2]), "+f"(c[3])
        : "r"(a[0]), "r"(a[1]), "r"(a[2]), "r"(a[3]), "r"(b0), "r"(b1));
}

// scale = 2^(14-e) if bound >= 2^14 else 1 (power of 2 -> exact)
__device__ __forceinline__ float w_scale(int c, int L) {
    float bound = __uint_as_float(g_amax_bits[c]) * g_B[L];
    int e; frexpf(bound, &e);
    return (e > 14) ? ldexpf(1.f, 14 - e) : 1.f;
}
__device__ __forceinline__ float w_invscale(int c, int L) {
    float bound = __uint_as_float(g_amax_bits[c]) * g_B[L];
    int e; frexpf(bound, &e);
    return (e > 14) ? ldexpf(1.f, e - 14) : 1.f;
}

// ---------------- kernel 1: fp32 conn -> fp16, one float4 per thread ----------------
__global__ void k_conv_half(const float4* __restrict__ src, int n4) {
    int i = blockIdx.x * blockDim.x + threadIdx.x;
    if (i >= n4) return;
    float4 v = src[i];
    __half2 h0 = __floats2half2_rn(v.x, v.y);
    __half2 h1 = __floats2half2_rn(v.z, v.w);
    uint2 u;
    u.x = *reinterpret_cast<uint32_t*>(&h0);
    u.y = *reinterpret_cast<uint32_t*>(&h1);
    reinterpret_cast<uint2*>(g_connH)[i] = u;
}

// ---------------- kernel 2: fused prep (filter transpose + bias + bounds + amax) -------
// blocks [0,384): transpose; [384,896): bias; 896,897: colsum bounds; 898: amax(x)
__global__ void k_prep(const float* __restrict__ x, const float* __restrict__ bond,
                       const float* __restrict__ f0, const float* __restrict__ f1) {
    __shared__ float sred[256];
    int b = blockIdx.x;
    int t = threadIdx.x;
    if (b < 384) {
        int idx = b * 256 + t;                 // < 98304 = 2*12*64*64
        int o = idx & 63;
        int d = (idx >> 6) & 63;
        int f = (idx >> 12) % NF;
        int L = idx / (NF * ND * ND);
        const float* src = L ? f1 : f0;
        g_Ft[idx] = src[o * FSTR + f * DP2 + d];
    } else if (b < 896) {
        int i = (b - 384) * 256 + t;           // < 131072 = 2048*64
        int a = i >> 6, o = i & 63;
        float bb[NF * 2];
#pragma unroll
        for (int j = 0; j < NF * 2; j++) bb[j] = bond[a * NF * 2 + j];
#pragma unroll
        for (int L = 0; L < 2; L++) {
            const float* flt = L ? f1 : f0;
            float s = 0.f;
#pragma unroll
            for (int f = 0; f < NF; f++) {
                s += bb[f * 2 + 0] * flt[o * FSTR + f * DP2 + ND + 0];
                s += bb[f * 2 + 1] * flt[o * FSTR + f * DP2 + ND + 1];
            }
            g_bias[L][i] = s;
        }
    } else if (b < 898) {
        int L = b - 896;
        const float* flt = L ? f1 : f0;
        float mx = 0.f;
        for (int i = t; i < ND * NF; i += 256) {
            int o = i / NF, f = i - o * NF;
            const float* p = flt + o * FSTR + f * DP2;
            float s = 0.f;
#pragma unroll
            for (int d = 0; d < ND; d++) s += fabsf(p[d]);
            mx = fmaxf(mx, s);
        }
        sred[t] = mx;
        __syncthreads();
        for (int off = 128; off; off >>= 1) {
            if (t < off) sred[t] = fmaxf(sred[t], sred[t + off]);
            __syncthreads();
        }
        if (t == 0) g_B[L] = sred[0];
    } else {
        float mx = 0.f;
        for (int i = t; i < NA * ND; i += 256) mx = fmaxf(mx, fabsf(x[i]));
        sred[t] = mx;
        __syncthreads();
        for (int off = 128; off; off >>= 1) {
            if (t < off) sred[t] = fmaxf(sred[t], sred[t + off]);
            __syncthreads();
        }
        if (t == 0) {
            g_amax_bits[0] = __float_as_uint(sred[0]);
            g_amax_bits[1] = 0u; g_amax_bits[2] = 0u;
            g_amax_bits[3] = 0u; g_amax_bits[4] = 0u;
        }
    }
}

// ---------------- kernel 3: WT[o][k] = scale * sum_d act[n,d] * Ft[L][f][d][o] ---------
// grid (64 o-blocks, 24 k-chunks), 256 threads, 4 k/thread -> coalesced fp16 writes
__global__ void k_W(const float* __restrict__ xin, int c, int L) {
    __shared__ float sF[NF * ND];
    int o = blockIdx.x;
    int t = threadIdx.x;
    const float* act = (c == 0) ? xin : g_act;
    float sc = w_scale(c, L);
    for (int i = t; i < NF * ND; i += 256)
        sF[i] = g_Ft[(L * NF * ND + i) * ND + o];
    __syncthreads();
    int kbase = blockIdx.y * 1024;
#pragma unroll
    for (int j = 0; j < 4; j++) {
        int k = kbase + j * 256 + t;
        int n = k / NF;
        int f = k - n * NF;
        const float4* ar = reinterpret_cast<const float4*>(act + n * ND);
        const float* fr = &sF[f * ND];
        float s = 0.f;
#pragma unroll
        for (int d4 = 0; d4 < 16; d4++) {
            float4 v = ar[d4];
            s += v.x * fr[d4 * 4 + 0] + v.y * fr[d4 * 4 + 1]
               + v.z * fr[d4 * 4 + 2] + v.w * fr[d4 * 4 + 3];
        }
        g_WT[(size_t)o * KTOT + k] = __float2half_rn(s * sc);
    }
}

// ---------------- kernel 4: split-K GEMM, 4-stage cp.async pipeline, KB=64 ------------
// grid (16 m-tiles, 8 splits), 256 threads = 8 warps (4x2), warp tile 32x32
__global__ __launch_bounds__(256, 1) void k_gemm() {
    extern __shared__ __align__(16) __half dyn[];
    __half* sAb = dyn;                          // [PIPE][MTILE][SPAD]
    __half* sBb = dyn + PIPE * MTILE * SPAD;    // [PIPE][ND][SPAD]

    int t = threadIdx.x;
    int mt = blockIdx.x, sp = blockIdx.y;
    int K0 = sp * KCHUNK;
    int lane = t & 31, w = t >> 5;
    int wm = w & 3, wn = w >> 2;

    float acc[2][4][4];
#pragma unroll
    for (int i = 0; i < 2; i++)
#pragma unroll
        for (int j = 0; j < 4; j++)
#pragma unroll
            for (int q = 0; q < 4; q++) acc[i][j][q] = 0.f;

    // stage = 64 halves per row: A 128 rows (1024 x 16B chunks), B 64 rows (512 chunks)
    auto LOAD = [&](int buf, int kb) {
        __half* A = sAb + buf * MTILE * SPAD;
        __half* B = sBb + buf * ND * SPAD;
#pragma unroll
        for (int j = 0; j < 4; j++) {
            int idx = j * 256 + t;
            int row = idx >> 3, c16 = idx & 7;
            const __half* src = g_connH + (size_t)(mt * MTILE + row) * KTOT + K0 + kb + c16 * 8;
            uint32_t dst = smem_u32(A + row * SPAD + c16 * 8);
            asm volatile("cp.async.cg.shared.global [%0], [%1], 16;" :: "r"(dst), "l"(src));
        }
#pragma unroll
        for (int j = 0; j < 2; j++) {
            int idx = j * 256 + t;
            int row = idx >> 3, c16 = idx & 7;
            const __half* src = g_WT + (size_t)row * KTOT + K0 + kb + c16 * 8;
            uint32_t dst = smem_u32(B + row * SPAD + c16 * 8);
            asm volatile("cp.async.cg.shared.global [%0], [%1], 16;" :: "r"(dst), "l"(src));
        }
        asm volatile("cp.async.commit_group;");
    };

    int ar = (lane & 7) + ((lane >> 3) & 1) * 8;   // A-fragment row within m16
    int asel = (lane >> 4) * 8;                    // A-fragment k-half
    int br = (lane & 7) + (lane >> 4) * 8;         // B n-row select
    int bsel = ((lane >> 3) & 1) * 8;              // B k-half

    auto COMPUTE = [&](int buf) {
        __half* A = sAb + buf * MTILE * SPAD;
        __half* B = sBb + buf * ND * SPAD;
#pragma unroll
        for (int kk = 0; kk < KB; kk += 16) {
            uint32_t a[2][4], b[2][4];
#pragma unroll
            for (int mi = 0; mi < 2; mi++) {
                uint32_t ad = smem_u32(A + (wm * 32 + mi * 16 + ar) * SPAD + kk + asel);
                ldmx4(a[mi], ad);
            }
#pragma unroll
            for (int p = 0; p < 2; p++) {
                uint32_t bd = smem_u32(B + (wn * 32 + p * 16 + br) * SPAD + kk + bsel);
                ldmx4(b[p], bd);
            }
#pragma unroll
            for (int mi = 0; mi < 2; mi++)
#pragma unroll
                for (int nt = 0; nt < 4; nt++)
                    mma16816(acc[mi][nt], a[mi], b[nt >> 1][(nt & 1) * 2], b[nt >> 1][(nt & 1) * 2 + 1]);
        }
    };

    // prologue: PIPE-1 stages in flight
#pragma unroll
    for (int s = 0; s < PIPE - 1; s++) LOAD(s, s * KB);

    int buf = 0;
    for (int s = 0; s < NSTAGES; s++) {
        asm volatile("cp.async.wait_group %0;" :: "n"(PIPE - 2));
        __syncthreads();
        int nxt = s + PIPE - 1;
        if (nxt < NSTAGES) {
            int wb = buf + (PIPE - 1); if (wb >= PIPE) wb -= PIPE;
            LOAD(wb, nxt * KB);
        } else {
            asm volatile("cp.async.commit_group;");   // keep group accounting invariant
        }
        COMPUTE(buf);
        if (++buf == PIPE) buf = 0;
    }

    // epilogue: write partials (unique writer per element -> deterministic)
    int g = lane >> 2, q = lane & 3;
    size_t pbase = (size_t)(mt * SPLITS + sp) * MTILE * ND;
#pragma unroll
    for (int mi = 0; mi < 2; mi++)
#pragma unroll
        for (int nt = 0; nt < 4; nt++) {
            int lrow = wm * 32 + mi * 16 + g;
            int col = wn * 32 + nt * 8 + q * 2;
            float2* p0 = reinterpret_cast<float2*>(&g_part[pbase + (size_t)lrow * ND + col]);
            *p0 = make_float2(acc[mi][nt][0], acc[mi][nt][1]);
            float2* p1 = reinterpret_cast<float2*>(&g_part[pbase + (size_t)(lrow + 8) * ND + col]);
            *p1 = make_float2(acc[mi][nt][2], acc[mi][nt][3]);
        }
}

// ---------------- kernel 5: split-K reduce * invscale + bias (+x) + ReLU + amax --------
__global__ void k_reduce(int c, int L, int addX, int writeOut,
                         const float* __restrict__ x, float* __restrict__ dout) {
    __shared__ float smax[8];
    int t = threadIdx.x;
    int idx = blockIdx.x * 256 + t;   // a*64 + o
    int a = idx >> 6;
    int o = idx & 63;
    int mtl = a >> 7;
    int lr = a & 127;
    float inv = w_invscale(c, L);
    float s = 0.f;
#pragma unroll
    for (int sp = 0; sp < SPLITS; sp++)
        s += g_part[(size_t)(mtl * SPLITS + sp) * MTILE * ND + (size_t)lr * ND + o];
    float v = s * inv + g_bias[L][idx];
    if (addX) v += x[idx];
    v = fmaxf(v, 0.f);
    g_act[idx] = v;
    if (writeOut) dout[idx] = v;
    float mx = v;
#pragma unroll
    for (int off = 16; off; off >>= 1)
        mx = fmaxf(mx, __shfl_xor_sync(0xffffffffu, mx, off));
    if ((t & 31) == 0) smax[t >> 5] = mx;
    __syncthreads();
    if (t == 0) {
#pragma unroll
        for (int ww = 1; ww < 8; ww++) mx = fmaxf(mx, smax[ww]);
        atomicMax(&g_amax_bits[c + 1], __float_as_uint(mx));
    }
}

// ---------------- launcher ----------------
extern "C" void kernel_launch(void* const* d_in, const int* in_sizes, int n_in,
                              void* d_out, int out_size) {
    const float* x    = (const float*)d_in[0];   // (2048, 64)
    const float* conn = (const float*)d_in[1];   // (2048, 2048, 12)
    const float* bond = (const float*)d_in[2];   // (2048, 12, 2)
    const float* f0   = (const float*)d_in[3];   // (64, 12, 66)
    const float* f1   = (const float*)d_in[4];   // (64, 12, 66)
    float* out = (float*)d_out;                  // (2048, 64)

    cudaFuncSetAttribute(k_gemm, cudaFuncAttributeMaxDynamicSharedMemorySize, GEMM_SMEM);

    int n4 = (NA * NA * NF) / 4;                           // 12,582,912
    k_conv_half<<<n4 / 256, 256>>>((const float4*)conn, n4);   // launch 1
    k_prep<<<899, 256>>>(x, bond, f0, f1);                     // launch 2

    // 4 chemconvs; k_gemm(c=0) is launch #4 -> lands in ncu's capture window
    for (int c = 0; c < 4; c++) {
        int L = c >> 1;
        k_W<<<dim3(64, 24), 256>>>(x, c, L);
        k_gemm<<<dim3(NA / MTILE, SPLITS), 256, GEMM_SMEM>>>();
        k_reduce<<<(NA * ND) / 256, 256>>>(c, L, c & 1, (c == 3) ? 1 : 0, x, out);
    }
}